// round 13
// baseline (speedup 1.0000x reference)
#include <cuda_runtime.h>
#include <cuda_bf16.h>
#include <math.h>

// Problem constants
#define BATCH   2
#define SEQ     1024
#define DMODEL  2048
#define NHEAD   32
#define NKVHEAD 8
#define DK      64
#define KVDIM   (NKVHEAD * DK)   // 512
#define NTOK    (BATCH * SEQ)    // 2048

// ---------------------------------------------------------------------------
// Scratch buffers
// ---------------------------------------------------------------------------
__device__ float g_Q[NTOK * DMODEL];   // 16 MB
__device__ float g_K[NTOK * KVDIM];    //  4 MB
__device__ float g_V[NTOK * KVDIM];    //  4 MB
__device__ float g_O[NTOK * DMODEL];   // 16 MB

// ---------------------------------------------------------------------------
// tf32 / async helpers
// ---------------------------------------------------------------------------
__device__ __forceinline__ float to_tf32(float x)
{
    unsigned u;
    asm volatile("cvt.rna.tf32.f32 %0, %1;\n" : "=r"(u) : "f"(x));
    return __uint_as_float(u);
}

__device__ __forceinline__ void mma_tf32_16x8x8(float d[4],
                                                const float a[4],
                                                const float b[2])
{
    asm volatile(
        "mma.sync.aligned.m16n8k8.row.col.f32.tf32.tf32.f32 "
        "{%0,%1,%2,%3}, {%4,%5,%6,%7}, {%8,%9}, {%0,%1,%2,%3};\n"
        : "+f"(d[0]), "+f"(d[1]), "+f"(d[2]), "+f"(d[3])
        : "r"(__float_as_uint(a[0])), "r"(__float_as_uint(a[1])),
          "r"(__float_as_uint(a[2])), "r"(__float_as_uint(a[3])),
          "r"(__float_as_uint(b[0])), "r"(__float_as_uint(b[1])));
}

__device__ __forceinline__ void cp_async16(void* smem_dst, const void* gmem_src)
{
    unsigned s = (unsigned)__cvta_generic_to_shared(smem_dst);
    asm volatile("cp.async.cg.shared.global [%0], [%1], 16;\n"
                 :: "r"(s), "l"(gmem_src));
}
__device__ __forceinline__ void cp_commit()
{
    asm volatile("cp.async.commit_group;\n");
}
template <int N>
__device__ __forceinline__ void cp_wait()
{
    asm volatile("cp.async.wait_group %0;\n" :: "n"(N));
}

// ---------------------------------------------------------------------------
// TF32 GEMM + bias (+ optional fused RoPE), cp.async 2-stage pipeline,
// 3 CTAs/SM for cross-CTA latency hiding.
// C[M,N] = A[M,K] @ W[K,N] + bias[N]; rope!=0 applies RoPE to the result
// (bit-identical arithmetic to the original standalone rope kernel).
// BM=BN=128, BK=32, 256 threads.
// smem: As[2][128][36] (m-major) + Bs[2][32][136] (k-major) = 71680 B.
// ---------------------------------------------------------------------------
#define GEMM_AS_STRIDE (128 * 36)
#define GEMM_BS_STRIDE (32 * 136)
#define GEMM_SMEM_BYTES ((2 * GEMM_AS_STRIDE + 2 * GEMM_BS_STRIDE) * 4)  // 71680

__device__ __forceinline__ void gemm_issue_tile(const float* __restrict__ A,
                                                const float* __restrict__ W,
                                                float* Ab, float* Bb,
                                                int bm, int bn, int k0,
                                                int N, int K, int tid)
{
#pragma unroll
    for (int t = 0; t < 4; t++) {
        int id = tid + t * 256;          // 0..1023
        int r  = id >> 3;                // 0..127
        int c4 = id & 7;                 // 0..7
        cp_async16(&Ab[r * 36 + c4 * 4],
                   &A[(size_t)(bm + r) * K + k0 + c4 * 4]);
    }
#pragma unroll
    for (int t = 0; t < 4; t++) {
        int id = tid + t * 256;
        int r  = id >> 5;                // 0..31 (k row)
        int c4 = id & 31;                // 0..31 (n/4)
        cp_async16(&Bb[r * 136 + c4 * 4],
                   &W[(size_t)(k0 + r) * N + bn + c4 * 4]);
    }
}

__global__ __launch_bounds__(256, 3)
void tf32_gemm_bias_kernel(const float* __restrict__ A,
                           const float* __restrict__ W,
                           const float* __restrict__ bias,
                           float* __restrict__ C,
                           int M, int N, int K, int rope)
{
    extern __shared__ float gs[];
    float* As = gs;                          // [2][128][36]
    float* Bs = gs + 2 * GEMM_AS_STRIDE;     // [2][32][136]

    const int tid  = threadIdx.x;
    const int warp = tid >> 5;
    const int lane = tid & 31;
    const int wm   = warp & 3;
    const int wn   = warp >> 2;
    const int grp  = lane >> 2;
    const int tig  = lane & 3;

    const int bm = blockIdx.y * 128;
    const int bn = blockIdx.x * 128;

    float d[2][8][4];
#pragma unroll
    for (int mt = 0; mt < 2; mt++)
#pragma unroll
        for (int nt = 0; nt < 8; nt++)
#pragma unroll
            for (int i = 0; i < 4; i++) d[mt][nt][i] = 0.f;

    const int ntiles = K >> 5;

    gemm_issue_tile(A, W, As, Bs, bm, bn, 0, N, K, tid);
    cp_commit();

    for (int t = 0; t < ntiles; t++) {
        const int buf = t & 1;
        if (t + 1 < ntiles) {
            gemm_issue_tile(A, W,
                            As + (buf ^ 1) * GEMM_AS_STRIDE,
                            Bs + (buf ^ 1) * GEMM_BS_STRIDE,
                            bm, bn, (t + 1) << 5, N, K, tid);
            cp_commit();
            cp_wait<1>();
        } else {
            cp_wait<0>();
        }
        __syncthreads();

        const float* Ab = As + buf * GEMM_AS_STRIDE;
        const float* Bb = Bs + buf * GEMM_BS_STRIDE;

#pragma unroll
        for (int ks = 0; ks < 4; ks++) {
            const int kb = ks * 8;
            float a[2][4];
#pragma unroll
            for (int mt = 0; mt < 2; mt++) {
                int row = wm * 32 + mt * 16 + grp;
                a[mt][0] = to_tf32(Ab[row * 36       + kb + tig]);
                a[mt][1] = to_tf32(Ab[(row + 8) * 36 + kb + tig]);
                a[mt][2] = to_tf32(Ab[row * 36       + kb + tig + 4]);
                a[mt][3] = to_tf32(Ab[(row + 8) * 36 + kb + tig + 4]);
            }
#pragma unroll
            for (int nt = 0; nt < 8; nt++) {
                float b[2];
                int col = wn * 64 + nt * 8 + grp;
                b[0] = to_tf32(Bb[(kb + tig) * 136     + col]);
                b[1] = to_tf32(Bb[(kb + tig + 4) * 136 + col]);
#pragma unroll
                for (int mt = 0; mt < 2; mt++)
                    mma_tf32_16x8x8(d[mt][nt], a[mt], b);
            }
        }
        __syncthreads();
    }

    // Epilogue: bias (+ optional RoPE) + store
#pragma unroll
    for (int mt = 0; mt < 2; mt++) {
        int row0 = bm + wm * 32 + mt * 16 + grp;
#pragma unroll
        for (int nt = 0; nt < 8; nt++) {
            int col = bn + wn * 64 + nt * 8 + tig * 2;
            float2 bv = *(const float2*)&bias[col];
            float2 o0, o1;
            o0.x = d[mt][nt][0] + bv.x;  o0.y = d[mt][nt][1] + bv.y;
            o1.x = d[mt][nt][2] + bv.x;  o1.y = d[mt][nt][3] + bv.y;
            if (rope) {
                int i = (col & 63) >> 1;
                float inv = __powf(10000.0f, -(float)i / 32.0f);
                float s0, c0, s1, c1;
                sincosf((float)(row0 & (SEQ - 1)) * inv, &s0, &c0);
                sincosf((float)((row0 + 8) & (SEQ - 1)) * inv, &s1, &c1);
                float e = o0.x, od = o0.y;
                o0.x = e * c0 - od * s0;  o0.y = e * s0 + od * c0;
                e = o1.x; od = o1.y;
                o1.x = e * c1 - od * s1;  o1.y = e * s1 + od * c1;
            }
            *(float2*)&C[(size_t)row0 * N + col]       = o0;
            *(float2*)&C[(size_t)(row0 + 8) * N + col] = o1;
        }
    }
}

// ---------------------------------------------------------------------------
// Flash attention via tf32 MMA (causal, GQA), cp.async double-buffered K/V,
// BALANCED: each block processes TWO q-tiles (qt = bx and 7-bx), so every
// block does exactly 18 kv-tiles of work. Grid (4, 64) = 256 blocks = one
// balanced wave at 2 CTAs/SM.
// smem: Ks[2][64][68] Vs[2][64][68] Ps[128][68] = 104448 B dynamic.
// ---------------------------------------------------------------------------
#define ATTN_KV_STRIDE (64 * 68)
#define ATTN_SMEM_BYTES ((4 * ATTN_KV_STRIDE + 128 * 68) * 4)   // 104448

__device__ __forceinline__ void attn_issue_tile(const float* __restrict__ Kbase,
                                                const float* __restrict__ Vbase,
                                                float* Kb, float* Vb,
                                                int jt, int tid)
{
#pragma unroll
    for (int t = 0; t < 4; t++) {
        int id = tid + t * 256;          // 0..1023
        int r  = id >> 4;                // 0..63
        int c4 = id & 15;                // 0..15
        cp_async16(&Kb[r * 68 + c4 * 4],
                   &Kbase[(size_t)(jt * 64 + r) * KVDIM + c4 * 4]);
        cp_async16(&Vb[r * 68 + c4 * 4],
                   &Vbase[(size_t)(jt * 64 + r) * KVDIM + c4 * 4]);
    }
}

__global__ __launch_bounds__(256, 2)
void attention_mma_kernel(const float* __restrict__ Q,
                          const float* __restrict__ K,
                          const float* __restrict__ V,
                          float* __restrict__ O)
{
    extern __shared__ float sm[];
    float* Ks = sm;                          // [2][64][68]
    float* Vs = sm + 2 * ATTN_KV_STRIDE;     // [2][64][68]
    float* Ps = sm + 4 * ATTN_KV_STRIDE;     // [128][68]

    const int tid  = threadIdx.x;
    const int warp = tid >> 5;
    const int lane = tid & 31;
    const int grp  = lane >> 2;     // 0..7
    const int tig  = lane & 3;      // 0..3

    const int bh = blockIdx.y;      // 0..63
    const int b  = bh >> 5;
    const int h  = bh & 31;
    const int g  = h >> 2;

    const float* Qbase = Q + (size_t)(b * SEQ) * DMODEL + h * DK;
    const float* Kbase = K + (size_t)(b * SEQ) * KVDIM + g * DK;
    const float* Vbase = V + (size_t)(b * SEQ) * KVDIM + g * DK;
    float*       Obase = O + (size_t)(b * SEQ) * DMODEL + h * DK;

    // Two q-tiles per block: qt = bx and 7 - bx (total work constant = 18 tiles)
#pragma unroll 1
    for (int qi = 0; qi < 2; qi++) {
        const int qt = qi ? (7 - blockIdx.x) : blockIdx.x;
        const int q0 = qt * 128 + warp * 16;

        // Q fragments in registers (scaled by 1/sqrt(dk), tf32)
        float qf[8][4];
        {
            const float* r0p = Qbase + (size_t)(q0 + grp) * DMODEL;
            const float* r1p = Qbase + (size_t)(q0 + grp + 8) * DMODEL;
#pragma unroll
            for (int ks = 0; ks < 8; ks++) {
                int d0 = ks * 8 + tig;
                qf[ks][0] = to_tf32(r0p[d0]     * 0.125f);
                qf[ks][1] = to_tf32(r1p[d0]     * 0.125f);
                qf[ks][2] = to_tf32(r0p[d0 + 4] * 0.125f);
                qf[ks][3] = to_tf32(r1p[d0 + 4] * 0.125f);
            }
        }

        float o[8][4];
#pragma unroll
        for (int nt = 0; nt < 8; nt++)
#pragma unroll
            for (int i = 0; i < 4; i++) o[nt][i] = 0.f;

        float m0 = -1e30f, m1 = -1e30f, l0 = 0.f, l1 = 0.f;

        const int jt_max = 2 * qt + 1;

        attn_issue_tile(Kbase, Vbase, Ks, Vs, 0, tid);
        cp_commit();

        for (int jt = 0; jt <= jt_max; jt++) {
            const int buf = jt & 1;
            if (jt + 1 <= jt_max) {
                attn_issue_tile(Kbase, Vbase,
                                Ks + (buf ^ 1) * ATTN_KV_STRIDE,
                                Vs + (buf ^ 1) * ATTN_KV_STRIDE,
                                jt + 1, tid);
                cp_commit();
                cp_wait<1>();
            } else {
                cp_wait<0>();
            }
            __syncthreads();

            const float* Kb = Ks + buf * ATTN_KV_STRIDE;
            const float* Vb = Vs + buf * ATTN_KV_STRIDE;

            // S = Q K^T
            float s[8][4];
#pragma unroll
            for (int nt = 0; nt < 8; nt++) {
                s[nt][0] = 0.f; s[nt][1] = 0.f; s[nt][2] = 0.f; s[nt][3] = 0.f;
#pragma unroll
                for (int ks = 0; ks < 8; ks++) {
                    float bf[2];
                    const float* kr = &Kb[(nt * 8 + grp) * 68 + ks * 8 + tig];
                    bf[0] = to_tf32(kr[0]);
                    bf[1] = to_tf32(kr[4]);
                    mma_tf32_16x8x8(s[nt], qf[ks], bf);
                }
            }

            // Causal mask
            if (jt >= 2 * qt) {
                const int r0g = q0 + grp;
                const int r1g = r0g + 8;
#pragma unroll
                for (int nt = 0; nt < 8; nt++) {
                    int c = jt * 64 + nt * 8 + tig * 2;
                    if (c     > r0g) s[nt][0] = -1e30f;
                    if (c + 1 > r0g) s[nt][1] = -1e30f;
                    if (c     > r1g) s[nt][2] = -1e30f;
                    if (c + 1 > r1g) s[nt][3] = -1e30f;
                }
            }

            // Online softmax
            float ml0 = -1e30f, ml1 = -1e30f;
#pragma unroll
            for (int nt = 0; nt < 8; nt++) {
                ml0 = fmaxf(ml0, fmaxf(s[nt][0], s[nt][1]));
                ml1 = fmaxf(ml1, fmaxf(s[nt][2], s[nt][3]));
            }
            ml0 = fmaxf(ml0, __shfl_xor_sync(0xffffffffu, ml0, 1));
            ml0 = fmaxf(ml0, __shfl_xor_sync(0xffffffffu, ml0, 2));
            ml1 = fmaxf(ml1, __shfl_xor_sync(0xffffffffu, ml1, 1));
            ml1 = fmaxf(ml1, __shfl_xor_sync(0xffffffffu, ml1, 2));

            const float mn0 = fmaxf(m0, ml0);
            const float mn1 = fmaxf(m1, ml1);
            const float sc0 = __expf(m0 - mn0);
            const float sc1 = __expf(m1 - mn1);
            m0 = mn0; m1 = mn1;

            float ls0 = 0.f, ls1 = 0.f;
            float* pr0 = &Ps[(warp * 16 + grp) * 68 + tig * 2];
            float* pr1 = &Ps[(warp * 16 + grp + 8) * 68 + tig * 2];
#pragma unroll
            for (int nt = 0; nt < 8; nt++) {
                float p0 = __expf(s[nt][0] - mn0);
                float p1 = __expf(s[nt][1] - mn0);
                float p2 = __expf(s[nt][2] - mn1);
                float p3 = __expf(s[nt][3] - mn1);
                ls0 += p0 + p1;
                ls1 += p2 + p3;
                *(float2*)&pr0[nt * 8] = make_float2(to_tf32(p0), to_tf32(p1));
                *(float2*)&pr1[nt * 8] = make_float2(to_tf32(p2), to_tf32(p3));
                o[nt][0] *= sc0; o[nt][1] *= sc0;
                o[nt][2] *= sc1; o[nt][3] *= sc1;
            }
            ls0 += __shfl_xor_sync(0xffffffffu, ls0, 1);
            ls0 += __shfl_xor_sync(0xffffffffu, ls0, 2);
            ls1 += __shfl_xor_sync(0xffffffffu, ls1, 1);
            ls1 += __shfl_xor_sync(0xffffffffu, ls1, 2);
            l0 = l0 * sc0 + ls0;
            l1 = l1 * sc1 + ls1;
            __syncwarp();   // Ps rows are per-warp private

            // O += P @ V
#pragma unroll
            for (int ks = 0; ks < 8; ks++) {
                float a[4];
                const float* p0p = &Ps[(warp * 16 + grp) * 68 + ks * 8 + tig];
                const float* p1p = &Ps[(warp * 16 + grp + 8) * 68 + ks * 8 + tig];
                a[0] = p0p[0];
                a[1] = p1p[0];
                a[2] = p0p[4];
                a[3] = p1p[4];
#pragma unroll
                for (int nt = 0; nt < 8; nt++) {
                    float bf[2];
                    const float* vp = &Vb[(ks * 8 + tig) * 68 + nt * 8 + grp];
                    bf[0] = to_tf32(vp[0]);
                    bf[1] = to_tf32(vp[4 * 68]);
                    mma_tf32_16x8x8(o[nt], a, bf);
                }
            }
            __syncthreads();   // protect K/V buffer before next issue overwrites
        }

        // Normalize and store
        const float linv0 = 1.0f / l0;
        const float linv1 = 1.0f / l1;
        float* o0p = Obase + (size_t)(q0 + grp) * DMODEL;
        float* o1p = Obase + (size_t)(q0 + grp + 8) * DMODEL;
#pragma unroll
        for (int nt = 0; nt < 8; nt++) {
            int c = nt * 8 + tig * 2;
            *(float2*)&o0p[c] = make_float2(o[nt][0] * linv0, o[nt][1] * linv0);
            *(float2*)&o1p[c] = make_float2(o[nt][2] * linv1, o[nt][3] * linv1);
        }
        __syncthreads();   // reuse of Ks/Vs/Ps by next q-tile
    }
}

// ---------------------------------------------------------------------------
// Launch
// ---------------------------------------------------------------------------
extern "C" void kernel_launch(void* const* d_in, const int* in_sizes, int n_in,
                              void* d_out, int out_size)
{
    const float* x  = (const float*)d_in[0];
    const float* Wq = (const float*)d_in[1];
    const float* bq = (const float*)d_in[2];
    const float* Wk = (const float*)d_in[3];
    const float* bk = (const float*)d_in[4];
    const float* Wv = (const float*)d_in[5];
    const float* bv = (const float*)d_in[6];
    const float* Wo = (const float*)d_in[7];
    const float* bo = (const float*)d_in[8];
    float* out = (float*)d_out;

    float *Qb, *Kb, *Vb, *Ob;
    cudaGetSymbolAddress((void**)&Qb, g_Q);
    cudaGetSymbolAddress((void**)&Kb, g_K);
    cudaGetSymbolAddress((void**)&Vb, g_V);
    cudaGetSymbolAddress((void**)&Ob, g_O);

    cudaFuncSetAttribute(tf32_gemm_bias_kernel,
                         cudaFuncAttributeMaxDynamicSharedMemorySize,
                         GEMM_SMEM_BYTES);
    cudaFuncSetAttribute(attention_mma_kernel,
                         cudaFuncAttributeMaxDynamicSharedMemorySize,
                         ATTN_SMEM_BYTES);

    // QKV projections (tf32 tensor cores, 2-stage cp.async, 3 CTAs/SM;
    // RoPE fused for Q/K)
    {
        dim3 grid(DMODEL / 128, NTOK / 128);
        tf32_gemm_bias_kernel<<<grid, 256, GEMM_SMEM_BYTES>>>(x, Wq, bq, Qb, NTOK, DMODEL, DMODEL, 1);
    }
    {
        dim3 grid(KVDIM / 128, NTOK / 128);
        tf32_gemm_bias_kernel<<<grid, 256, GEMM_SMEM_BYTES>>>(x, Wk, bk, Kb, NTOK, KVDIM, DMODEL, 1);
        tf32_gemm_bias_kernel<<<grid, 256, GEMM_SMEM_BYTES>>>(x, Wv, bv, Vb, NTOK, KVDIM, DMODEL, 0);
    }

    // Attention (tf32 MMA, double-buffered K/V, balanced q-tile pairing)
    {
        dim3 grid(SEQ / 256, BATCH * NHEAD);   // (4, 64)
        attention_mma_kernel<<<grid, 256, ATTN_SMEM_BYTES>>>(Qb, Kb, Vb, Ob);
    }

    // Output projection
    {
        dim3 grid(DMODEL / 128, NTOK / 128);
        tf32_gemm_bias_kernel<<<grid, 256, GEMM_SMEM_BYTES>>>(Ob, Wo, bo, out, NTOK, DMODEL, DMODEL, 0);
    }
}

// round 15
// speedup vs baseline: 2.1556x; 2.1556x over previous
#include <cuda_runtime.h>
#include <cuda_bf16.h>
#include <math.h>

// Problem constants
#define BATCH   2
#define SEQ     1024
#define DMODEL  2048
#define NHEAD   32
#define NKVHEAD 8
#define DK      64
#define KVDIM   (NKVHEAD * DK)   // 512
#define NTOK    (BATCH * SEQ)    // 2048

// ---------------------------------------------------------------------------
// Scratch buffers
// ---------------------------------------------------------------------------
__device__ float g_Q[NTOK * DMODEL];   // 16 MB
__device__ float g_K[NTOK * KVDIM];    //  4 MB
__device__ float g_V[NTOK * KVDIM];    //  4 MB
__device__ float g_O[NTOK * DMODEL];   // 16 MB

// ---------------------------------------------------------------------------
// tf32 / async helpers
// ---------------------------------------------------------------------------
__device__ __forceinline__ float to_tf32(float x)
{
    unsigned u;
    asm volatile("cvt.rna.tf32.f32 %0, %1;\n" : "=r"(u) : "f"(x));
    return __uint_as_float(u);
}

__device__ __forceinline__ void mma_tf32_16x8x8(float d[4],
                                                const float a[4],
                                                const float b[2])
{
    asm volatile(
        "mma.sync.aligned.m16n8k8.row.col.f32.tf32.tf32.f32 "
        "{%0,%1,%2,%3}, {%4,%5,%6,%7}, {%8,%9}, {%0,%1,%2,%3};\n"
        : "+f"(d[0]), "+f"(d[1]), "+f"(d[2]), "+f"(d[3])
        : "r"(__float_as_uint(a[0])), "r"(__float_as_uint(a[1])),
          "r"(__float_as_uint(a[2])), "r"(__float_as_uint(a[3])),
          "r"(__float_as_uint(b[0])), "r"(__float_as_uint(b[1])));
}

__device__ __forceinline__ void cp_async16(void* smem_dst, const void* gmem_src)
{
    unsigned s = (unsigned)__cvta_generic_to_shared(smem_dst);
    asm volatile("cp.async.cg.shared.global [%0], [%1], 16;\n"
                 :: "r"(s), "l"(gmem_src));
}
__device__ __forceinline__ void cp_commit()
{
    asm volatile("cp.async.commit_group;\n");
}
template <int N>
__device__ __forceinline__ void cp_wait()
{
    asm volatile("cp.async.wait_group %0;\n" :: "n"(N));
}

// ---------------------------------------------------------------------------
// Core TF32 GEMM tile routine (R10-validated 2-stage cp.async pipeline,
// launch_bounds(256,2), no spills) + R12-validated bit-identical RoPE
// epilogue. Computes one 128x128 C-tile:
//   C[bm:bm+128, bn:bn+128] = A[bm:, :K] @ W[:, bn:] + bias[bn:]  (+ RoPE)
// smem: As[2][128][36] (m-major) + Bs[2][32][136] (k-major) = 71680 B.
// ---------------------------------------------------------------------------
#define GEMM_AS_STRIDE (128 * 36)
#define GEMM_BS_STRIDE (32 * 136)
#define GEMM_SMEM_BYTES ((2 * GEMM_AS_STRIDE + 2 * GEMM_BS_STRIDE) * 4)  // 71680

__device__ __forceinline__ void gemm_issue_tile(const float* __restrict__ A,
                                                const float* __restrict__ W,
                                                float* Ab, float* Bb,
                                                int bm, int bn, int k0,
                                                int N, int K, int tid)
{
#pragma unroll
    for (int t = 0; t < 4; t++) {
        int id = tid + t * 256;          // 0..1023
        int r  = id >> 3;                // 0..127
        int c4 = id & 7;                 // 0..7
        cp_async16(&Ab[r * 36 + c4 * 4],
                   &A[(size_t)(bm + r) * K + k0 + c4 * 4]);
    }
#pragma unroll
    for (int t = 0; t < 4; t++) {
        int id = tid + t * 256;
        int r  = id >> 5;                // 0..31 (k row)
        int c4 = id & 31;                // 0..31 (n/4)
        cp_async16(&Bb[r * 136 + c4 * 4],
                   &W[(size_t)(k0 + r) * N + bn + c4 * 4]);
    }
}

__device__ __forceinline__ void gemm_tile_body(const float* __restrict__ A,
                                               const float* __restrict__ W,
                                               const float* __restrict__ bias,
                                               float* __restrict__ C,
                                               int bm, int bn,
                                               int N, int K, int rope,
                                               float* As, float* Bs)
{
    const int tid  = threadIdx.x;
    const int warp = tid >> 5;
    const int lane = tid & 31;
    const int wm   = warp & 3;
    const int wn   = warp >> 2;
    const int grp  = lane >> 2;
    const int tig  = lane & 3;

    float d[2][8][4];
#pragma unroll
    for (int mt = 0; mt < 2; mt++)
#pragma unroll
        for (int nt = 0; nt < 8; nt++)
#pragma unroll
            for (int i = 0; i < 4; i++) d[mt][nt][i] = 0.f;

    const int ntiles = K >> 5;

    gemm_issue_tile(A, W, As, Bs, bm, bn, 0, N, K, tid);
    cp_commit();

    for (int t = 0; t < ntiles; t++) {
        const int buf = t & 1;
        if (t + 1 < ntiles) {
            gemm_issue_tile(A, W,
                            As + (buf ^ 1) * GEMM_AS_STRIDE,
                            Bs + (buf ^ 1) * GEMM_BS_STRIDE,
                            bm, bn, (t + 1) << 5, N, K, tid);
            cp_commit();
            cp_wait<1>();
        } else {
            cp_wait<0>();
        }
        __syncthreads();

        const float* Ab = As + buf * GEMM_AS_STRIDE;
        const float* Bb = Bs + buf * GEMM_BS_STRIDE;

#pragma unroll
        for (int ks = 0; ks < 4; ks++) {
            const int kb = ks * 8;
            float a[2][4];
#pragma unroll
            for (int mt = 0; mt < 2; mt++) {
                int row = wm * 32 + mt * 16 + grp;
                a[mt][0] = to_tf32(Ab[row * 36       + kb + tig]);
                a[mt][1] = to_tf32(Ab[(row + 8) * 36 + kb + tig]);
                a[mt][2] = to_tf32(Ab[row * 36       + kb + tig + 4]);
                a[mt][3] = to_tf32(Ab[(row + 8) * 36 + kb + tig + 4]);
            }
#pragma unroll
            for (int nt = 0; nt < 8; nt++) {
                float b[2];
                int col = wn * 64 + nt * 8 + grp;
                b[0] = to_tf32(Bb[(kb + tig) * 136     + col]);
                b[1] = to_tf32(Bb[(kb + tig + 4) * 136 + col]);
#pragma unroll
                for (int mt = 0; mt < 2; mt++)
                    mma_tf32_16x8x8(d[mt][nt], a[mt], b);
            }
        }
        __syncthreads();
    }

    // Epilogue: bias (+ optional RoPE) + store
#pragma unroll
    for (int mt = 0; mt < 2; mt++) {
        int row0 = bm + wm * 32 + mt * 16 + grp;
#pragma unroll
        for (int nt = 0; nt < 8; nt++) {
            int col = bn + wn * 64 + nt * 8 + tig * 2;
            float2 bv = *(const float2*)&bias[col];
            float2 o0, o1;
            o0.x = d[mt][nt][0] + bv.x;  o0.y = d[mt][nt][1] + bv.y;
            o1.x = d[mt][nt][2] + bv.x;  o1.y = d[mt][nt][3] + bv.y;
            if (rope) {
                int i = (col & 63) >> 1;
                float inv = __powf(10000.0f, -(float)i / 32.0f);
                float s0, c0, s1, c1;
                sincosf((float)(row0 & (SEQ - 1)) * inv, &s0, &c0);
                sincosf((float)((row0 + 8) & (SEQ - 1)) * inv, &s1, &c1);
                float e = o0.x, od = o0.y;
                o0.x = e * c0 - od * s0;  o0.y = e * s0 + od * c0;
                e = o1.x; od = o1.y;
                o1.x = e * c1 - od * s1;  o1.y = e * s1 + od * c1;
            }
            *(float2*)&C[(size_t)row0 * N + col]       = o0;
            *(float2*)&C[(size_t)(row0 + 8) * N + col] = o1;
        }
    }
}

// ---------------------------------------------------------------------------
// Merged QKV projection: one launch, grid (24, 16).
//   bx in [0,16)  -> Q tile col bx      (N=DMODEL, rope=1)
//   bx in [16,20) -> K tile col bx-16   (N=KVDIM,  rope=1)
//   bx in [20,24) -> V tile col bx-20   (N=KVDIM,  rope=0)
// Each block computes exactly the same tile it did in the separate-launch
// version -> bit-identical numerics.
// ---------------------------------------------------------------------------
__global__ __launch_bounds__(256, 2)
void qkv_gemm_kernel(const float* __restrict__ x,
                     const float* __restrict__ Wq, const float* __restrict__ bq,
                     const float* __restrict__ Wk, const float* __restrict__ bk,
                     const float* __restrict__ Wv, const float* __restrict__ bv,
                     float* __restrict__ Qb, float* __restrict__ Kb,
                     float* __restrict__ Vb)
{
    extern __shared__ float gs[];
    float* As = gs;
    float* Bs = gs + 2 * GEMM_AS_STRIDE;

    const int bx = blockIdx.x;
    const int bm = blockIdx.y * 128;

    if (bx < 16) {
        gemm_tile_body(x, Wq, bq, Qb, bm, bx * 128, DMODEL, DMODEL, 1, As, Bs);
    } else if (bx < 20) {
        gemm_tile_body(x, Wk, bk, Kb, bm, (bx - 16) * 128, KVDIM, DMODEL, 1, As, Bs);
    } else {
        gemm_tile_body(x, Wv, bv, Vb, bm, (bx - 20) * 128, KVDIM, DMODEL, 0, As, Bs);
    }
}

// Single-output GEMM (used for the output projection)
__global__ __launch_bounds__(256, 2)
void tf32_gemm_bias_kernel(const float* __restrict__ A,
                           const float* __restrict__ W,
                           const float* __restrict__ bias,
                           float* __restrict__ C,
                           int M, int N, int K, int rope)
{
    extern __shared__ float gs[];
    float* As = gs;
    float* Bs = gs + 2 * GEMM_AS_STRIDE;
    gemm_tile_body(A, W, bias, C, blockIdx.y * 128, blockIdx.x * 128,
                   N, K, rope, As, Bs);
}

// ---------------------------------------------------------------------------
// Flash attention via tf32 MMA (causal, GQA), cp.async double-buffered K/V,
// BALANCED q-tile pairing (R13-measured: 109.9 us): each block handles
// qt = bx and 7-bx => every block does exactly 18 kv-tiles.
// Grid (4, 64) = 256 blocks.
// smem: Ks[2][64][68] Vs[2][64][68] Ps[128][68] = 104448 B dynamic.
// ---------------------------------------------------------------------------
#define ATTN_KV_STRIDE (64 * 68)
#define ATTN_SMEM_BYTES ((4 * ATTN_KV_STRIDE + 128 * 68) * 4)   // 104448

__device__ __forceinline__ void attn_issue_tile(const float* __restrict__ Kbase,
                                                const float* __restrict__ Vbase,
                                                float* Kb, float* Vb,
                                                int jt, int tid)
{
#pragma unroll
    for (int t = 0; t < 4; t++) {
        int id = tid + t * 256;          // 0..1023
        int r  = id >> 4;                // 0..63
        int c4 = id & 15;                // 0..15
        cp_async16(&Kb[r * 68 + c4 * 4],
                   &Kbase[(size_t)(jt * 64 + r) * KVDIM + c4 * 4]);
        cp_async16(&Vb[r * 68 + c4 * 4],
                   &Vbase[(size_t)(jt * 64 + r) * KVDIM + c4 * 4]);
    }
}

__global__ __launch_bounds__(256, 2)
void attention_mma_kernel(const float* __restrict__ Q,
                          const float* __restrict__ K,
                          const float* __restrict__ V,
                          float* __restrict__ O)
{
    extern __shared__ float sm[];
    float* Ks = sm;                          // [2][64][68]
    float* Vs = sm + 2 * ATTN_KV_STRIDE;     // [2][64][68]
    float* Ps = sm + 4 * ATTN_KV_STRIDE;     // [128][68]

    const int tid  = threadIdx.x;
    const int warp = tid >> 5;
    const int lane = tid & 31;
    const int grp  = lane >> 2;     // 0..7
    const int tig  = lane & 3;      // 0..3

    const int bh = blockIdx.y;      // 0..63
    const int b  = bh >> 5;
    const int h  = bh & 31;
    const int g  = h >> 2;

    const float* Qbase = Q + (size_t)(b * SEQ) * DMODEL + h * DK;
    const float* Kbase = K + (size_t)(b * SEQ) * KVDIM + g * DK;
    const float* Vbase = V + (size_t)(b * SEQ) * KVDIM + g * DK;
    float*       Obase = O + (size_t)(b * SEQ) * DMODEL + h * DK;

    // Two q-tiles per block: qt = bx and 7 - bx (constant 18 tiles of work)
#pragma unroll 1
    for (int qi = 0; qi < 2; qi++) {
        const int qt = qi ? (7 - blockIdx.x) : blockIdx.x;
        const int q0 = qt * 128 + warp * 16;

        // Q fragments in registers (scaled by 1/sqrt(dk), tf32)
        float qf[8][4];
        {
            const float* r0p = Qbase + (size_t)(q0 + grp) * DMODEL;
            const float* r1p = Qbase + (size_t)(q0 + grp + 8) * DMODEL;
#pragma unroll
            for (int ks = 0; ks < 8; ks++) {
                int d0 = ks * 8 + tig;
                qf[ks][0] = to_tf32(r0p[d0]     * 0.125f);
                qf[ks][1] = to_tf32(r1p[d0]     * 0.125f);
                qf[ks][2] = to_tf32(r0p[d0 + 4] * 0.125f);
                qf[ks][3] = to_tf32(r1p[d0 + 4] * 0.125f);
            }
        }

        float o[8][4];
#pragma unroll
        for (int nt = 0; nt < 8; nt++)
#pragma unroll
            for (int i = 0; i < 4; i++) o[nt][i] = 0.f;

        float m0 = -1e30f, m1 = -1e30f, l0 = 0.f, l1 = 0.f;

        const int jt_max = 2 * qt + 1;

        attn_issue_tile(Kbase, Vbase, Ks, Vs, 0, tid);
        cp_commit();

        for (int jt = 0; jt <= jt_max; jt++) {
            const int buf = jt & 1;
            if (jt + 1 <= jt_max) {
                attn_issue_tile(Kbase, Vbase,
                                Ks + (buf ^ 1) * ATTN_KV_STRIDE,
                                Vs + (buf ^ 1) * ATTN_KV_STRIDE,
                                jt + 1, tid);
                cp_commit();
                cp_wait<1>();
            } else {
                cp_wait<0>();
            }
            __syncthreads();

            const float* Kb = Ks + buf * ATTN_KV_STRIDE;
            const float* Vb = Vs + buf * ATTN_KV_STRIDE;

            // S = Q K^T
            float s[8][4];
#pragma unroll
            for (int nt = 0; nt < 8; nt++) {
                s[nt][0] = 0.f; s[nt][1] = 0.f; s[nt][2] = 0.f; s[nt][3] = 0.f;
#pragma unroll
                for (int ks = 0; ks < 8; ks++) {
                    float bf[2];
                    const float* kr = &Kb[(nt * 8 + grp) * 68 + ks * 8 + tig];
                    bf[0] = to_tf32(kr[0]);
                    bf[1] = to_tf32(kr[4]);
                    mma_tf32_16x8x8(s[nt], qf[ks], bf);
                }
            }

            // Causal mask
            if (jt >= 2 * qt) {
                const int r0g = q0 + grp;
                const int r1g = r0g + 8;
#pragma unroll
                for (int nt = 0; nt < 8; nt++) {
                    int c = jt * 64 + nt * 8 + tig * 2;
                    if (c     > r0g) s[nt][0] = -1e30f;
                    if (c + 1 > r0g) s[nt][1] = -1e30f;
                    if (c     > r1g) s[nt][2] = -1e30f;
                    if (c + 1 > r1g) s[nt][3] = -1e30f;
                }
            }

            // Online softmax
            float ml0 = -1e30f, ml1 = -1e30f;
#pragma unroll
            for (int nt = 0; nt < 8; nt++) {
                ml0 = fmaxf(ml0, fmaxf(s[nt][0], s[nt][1]));
                ml1 = fmaxf(ml1, fmaxf(s[nt][2], s[nt][3]));
            }
            ml0 = fmaxf(ml0, __shfl_xor_sync(0xffffffffu, ml0, 1));
            ml0 = fmaxf(ml0, __shfl_xor_sync(0xffffffffu, ml0, 2));
            ml1 = fmaxf(ml1, __shfl_xor_sync(0xffffffffu, ml1, 1));
            ml1 = fmaxf(ml1, __shfl_xor_sync(0xffffffffu, ml1, 2));

            const float mn0 = fmaxf(m0, ml0);
            const float mn1 = fmaxf(m1, ml1);
            const float sc0 = __expf(m0 - mn0);
            const float sc1 = __expf(m1 - mn1);
            m0 = mn0; m1 = mn1;

            float ls0 = 0.f, ls1 = 0.f;
            float* pr0 = &Ps[(warp * 16 + grp) * 68 + tig * 2];
            float* pr1 = &Ps[(warp * 16 + grp + 8) * 68 + tig * 2];
#pragma unroll
            for (int nt = 0; nt < 8; nt++) {
                float p0 = __expf(s[nt][0] - mn0);
                float p1 = __expf(s[nt][1] - mn0);
                float p2 = __expf(s[nt][2] - mn1);
                float p3 = __expf(s[nt][3] - mn1);
                ls0 += p0 + p1;
                ls1 += p2 + p3;
                *(float2*)&pr0[nt * 8] = make_float2(to_tf32(p0), to_tf32(p1));
                *(float2*)&pr1[nt * 8] = make_float2(to_tf32(p2), to_tf32(p3));
                o[nt][0] *= sc0; o[nt][1] *= sc0;
                o[nt][2] *= sc1; o[nt][3] *= sc1;
            }
            ls0 += __shfl_xor_sync(0xffffffffu, ls0, 1);
            ls0 += __shfl_xor_sync(0xffffffffu, ls0, 2);
            ls1 += __shfl_xor_sync(0xffffffffu, ls1, 1);
            ls1 += __shfl_xor_sync(0xffffffffu, ls1, 2);
            l0 = l0 * sc0 + ls0;
            l1 = l1 * sc1 + ls1;
            __syncwarp();   // Ps rows are per-warp private

            // O += P @ V
#pragma unroll
            for (int ks = 0; ks < 8; ks++) {
                float a[4];
                const float* p0p = &Ps[(warp * 16 + grp) * 68 + ks * 8 + tig];
                const float* p1p = &Ps[(warp * 16 + grp + 8) * 68 + ks * 8 + tig];
                a[0] = p0p[0];
                a[1] = p1p[0];
                a[2] = p0p[4];
                a[3] = p1p[4];
#pragma unroll
                for (int nt = 0; nt < 8; nt++) {
                    float bf[2];
                    const float* vp = &Vb[(ks * 8 + tig) * 68 + nt * 8 + grp];
                    bf[0] = to_tf32(vp[0]);
                    bf[1] = to_tf32(vp[4 * 68]);
                    mma_tf32_16x8x8(o[nt], a, bf);
                }
            }
            __syncthreads();   // protect K/V buffer before next issue overwrites
        }

        // Normalize and store
        const float linv0 = 1.0f / l0;
        const float linv1 = 1.0f / l1;
        float* o0p = Obase + (size_t)(q0 + grp) * DMODEL;
        float* o1p = Obase + (size_t)(q0 + grp + 8) * DMODEL;
#pragma unroll
        for (int nt = 0; nt < 8; nt++) {
            int c = nt * 8 + tig * 2;
            *(float2*)&o0p[c] = make_float2(o[nt][0] * linv0, o[nt][1] * linv0);
            *(float2*)&o1p[c] = make_float2(o[nt][2] * linv1, o[nt][3] * linv1);
        }
        __syncthreads();   // reuse of Ks/Vs/Ps by next q-tile
    }
}

// ---------------------------------------------------------------------------
// Launch
// ---------------------------------------------------------------------------
extern "C" void kernel_launch(void* const* d_in, const int* in_sizes, int n_in,
                              void* d_out, int out_size)
{
    const float* x  = (const float*)d_in[0];
    const float* Wq = (const float*)d_in[1];
    const float* bq = (const float*)d_in[2];
    const float* Wk = (const float*)d_in[3];
    const float* bk = (const float*)d_in[4];
    const float* Wv = (const float*)d_in[5];
    const float* bv = (const float*)d_in[6];
    const float* Wo = (const float*)d_in[7];
    const float* bo = (const float*)d_in[8];
    float* out = (float*)d_out;

    float *Qb, *Kb, *Vb, *Ob;
    cudaGetSymbolAddress((void**)&Qb, g_Q);
    cudaGetSymbolAddress((void**)&Kb, g_K);
    cudaGetSymbolAddress((void**)&Vb, g_V);
    cudaGetSymbolAddress((void**)&Ob, g_O);

    cudaFuncSetAttribute(qkv_gemm_kernel,
                         cudaFuncAttributeMaxDynamicSharedMemorySize,
                         GEMM_SMEM_BYTES);
    cudaFuncSetAttribute(tf32_gemm_bias_kernel,
                         cudaFuncAttributeMaxDynamicSharedMemorySize,
                         GEMM_SMEM_BYTES);
    cudaFuncSetAttribute(attention_mma_kernel,
                         cudaFuncAttributeMaxDynamicSharedMemorySize,
                         ATTN_SMEM_BYTES);

    // Merged QKV projections (one launch, RoPE fused for Q/K)
    {
        dim3 grid(24, NTOK / 128);   // [0,16)=Q, [16,20)=K, [20,24)=V
        qkv_gemm_kernel<<<grid, 256, GEMM_SMEM_BYTES>>>(
            x, Wq, bq, Wk, bk, Wv, bv, Qb, Kb, Vb);
    }

    // Attention (tf32 MMA, double-buffered K/V, balanced q-tile pairing)
    {
        dim3 grid(SEQ / 256, BATCH * NHEAD);   // (4, 64)
        attention_mma_kernel<<<grid, 256, ATTN_SMEM_BYTES>>>(Qb, Kb, Vb, Ob);
    }

    // Output projection
    {
        dim3 grid(DMODEL / 128, NTOK / 128);
        tf32_gemm_bias_kernel<<<grid, 256, GEMM_SMEM_BYTES>>>(Ob, Wo, bo, out, NTOK, DMODEL, DMODEL, 0);
    }
}